// round 14
// baseline (speedup 1.0000x reference)
#include <cuda_runtime.h>
#include <cuda_fp16.h>
#include <cstdint>
#include <cstddef>

#define FULL_MASK 0xFFFFFFFFu

// Problem constants: B=128, N=196, C=768, h=12, e=64, frames=16
// tokens M = 25088 ; b = 8 ; S = 3136 ; bh = 96
static const int M_TOK = 25088;

// ---------------------------------------------------------------------------
// Scratch (allocation-free: __device__ globals)
// ---------------------------------------------------------------------------
__device__ __half g_qkv[(size_t)25088 * 2304]; // [tok][3*C] (q|k|v) fp16, q/k ReLU'd
__device__ float g_ksum[96 * 64];               // [bh][e]
__device__ float g_kvp[7 * 96 * 64 * 64];       // S-split partials
__device__ float g_ksump[7 * 96 * 64];
__device__ uint2 g_kvfrag[96 * 2048];           // [bh][part(2)][kc(4)][nt(8)][lane(32)] uint2

// fp16 fragment-ordered tiles (hi only).
// A: [mb][kt][mtile(8)][512B] -> chunk 4KB ; B: [nb][kt][ntile(16)][256B] -> 4KB
__device__ uint4 g_a1s[(25088 / 16) * (768 / 16) * 32];   // 38.5 MB (x)
__device__ uint4 g_a2s[(25088 / 16) * (768 / 16) * 32];   // 38.5 MB (attn, by vo_gemm)
__device__ uint4 g_b1s[(2304 / 8) * (768 / 16) * 16];     // 3.5 MB (Wqkv)
__device__ uint4 g_b2s[(768 / 8) * (768 / 16) * 16];      // 1.2 MB (Wproj)

// ---------------------------------------------------------------------------
__device__ __forceinline__ uint32_t smem_u32(const void* p) {
    uint32_t r;
    asm("{.reg .u64 t; cvta.to.shared.u64 t, %1; cvt.u32.u64 %0, t;}" : "=r"(r) : "l"(p));
    return r;
}

// Split float2 -> hi f16x2 (return) + residual f16x2 (lo). low half = .x
__device__ __forceinline__ uint32_t split2h(float2 v, uint32_t& lo) {
    __half2 h = __float22half2_rn(v);
    float2 back = __half22float2(h);
    __half2 l = __float22half2_rn(make_float2(v.x - back.x, v.y - back.y));
    lo = *(uint32_t*)&l;
    return *(uint32_t*)&h;
}
__device__ __forceinline__ uint32_t cvt2h(float2 v) {
    __half2 h = __float22half2_rn(v);
    return *(uint32_t*)&h;
}

// mma.sync m16n8k16 fp16: d += a*b (row.col, f32 accum)
__device__ __forceinline__ void mma16(float4& d, uint4 a, uint2 b) {
    asm volatile(
        "mma.sync.aligned.m16n8k16.row.col.f32.f16.f16.f32 "
        "{%0,%1,%2,%3}, {%4,%5,%6,%7}, {%8,%9}, {%0,%1,%2,%3};"
        : "+f"(d.x), "+f"(d.y), "+f"(d.z), "+f"(d.w)
        : "r"(a.x), "r"(a.y), "r"(a.z), "r"(a.w), "r"(b.x), "r"(b.y));
}

// ---------------------------------------------------------------------------
// split_a: fp32 [M][K] -> A-frag tiles (hi fp16), m16n8k16 A layout.
// ---------------------------------------------------------------------------
__global__ __launch_bounds__(256) void split_a(const float* __restrict__ src,
                                               uint4* __restrict__ dst, int K)
{
    const int NKT  = K >> 4;
    const int strip = blockIdx.x;
    const int warp = threadIdx.x >> 5, lane = threadIdx.x & 31;
    const int mb = strip >> 3, mt = strip & 7;
    const int c2 = (lane & 3) * 2;
    const float* row0 = src + (size_t)(strip * 16 + (lane >> 2)) * K;
    const float* row1 = row0 + (size_t)8 * K;
    char* base = (char*)dst;

    for (int kt = warp; kt < NKT; kt += 8) {
        const int kb = kt * 16;
        uint32_t h0 = cvt2h(*(const float2*)(row0 + kb + c2));
        uint32_t h1 = cvt2h(*(const float2*)(row1 + kb + c2));
        uint32_t h2 = cvt2h(*(const float2*)(row0 + kb + c2 + 8));
        uint32_t h3 = cvt2h(*(const float2*)(row1 + kb + c2 + 8));
        size_t off = ((size_t)(mb * NKT + kt) << 12) + mt * 512 + lane * 16;
        *(uint4*)(base + off) = make_uint4(h0, h1, h2, h3);
    }
}

// ---------------------------------------------------------------------------
// split_b: fp32 [N][K] -> B-frag tiles (hi fp16), m16n8k16 B layout.
// ---------------------------------------------------------------------------
__global__ __launch_bounds__(256) void split_b(const float* __restrict__ src,
                                               uint4* __restrict__ dst, int K)
{
    const int NKT  = K >> 4;
    const int strip = blockIdx.x;
    const int warp = threadIdx.x >> 5, lane = threadIdx.x & 31;
    const int nb = strip >> 4, nt = strip & 15;
    const int c2 = (lane & 3) * 2;
    const float* row = src + (size_t)(strip * 8 + (lane >> 2)) * K;
    char* base = (char*)dst;

    for (int kt = warp; kt < NKT; kt += 8) {
        const int kb = kt * 16;
        uint32_t h0 = cvt2h(*(const float2*)(row + kb + c2));
        uint32_t h1 = cvt2h(*(const float2*)(row + kb + c2 + 8));
        size_t off = ((size_t)(nb * NKT + kt) << 12) + nt * 256 + lane * 8;
        *(uint2*)(base + off) = make_uint2(h0, h1);
    }
}

// ---------------------------------------------------------------------------
// fp16 1-term HMMA GEMM on pre-split tiles. 6-stage cp.async ring (48KB),
// ONE barrier per 2 chunks (stage distance makes the trailing barrier
// unnecessary: issue(kc+4/5) writes stages kc-2/kc-1 (mod 6), which all warps
// finished before this iteration's barrier). 256 threads, 128x128 tile, BK=16,
// 2 CTAs/SM. Output: half (Ch, ReLU<relu_limit) or fp32 (C, +bias).
// ---------------------------------------------------------------------------
__global__ __launch_bounds__(256, 2) void gemm_f16(
    const uint4* __restrict__ As, const uint4* __restrict__ Bs,
    float* __restrict__ C, __half* __restrict__ Ch,
    int M, int N, int K, const float* __restrict__ bias, int relu_limit)
{
    __shared__ char smem[6 * 8192];   // 48KB static (max)

    const int tid  = threadIdx.x;
    const int lane = tid & 31;
    const int warp = tid >> 5;
    const int mb   = blockIdx.y;
    const int nb   = blockIdx.x;
    const int NKT  = K >> 4;          // 48 (divisible by 6)
    const uint32_t sb = smem_u32(smem);

    const char* Abase = (const char*)As + ((size_t)mb * NKT << 12);
    const char* Bbase = (const char*)Bs + ((size_t)nb * NKT << 12);

    auto issue = [&](int kc) {
        const char* asrc = Abase + ((size_t)kc << 12);
        const char* bsrc = Bbase + ((size_t)kc << 12);
        const uint32_t dst0 = sb + (kc % 6) * 8192;
        asm volatile("cp.async.ca.shared.global [%0], [%1], 16;"
                     :: "r"(dst0 + tid * 16), "l"(asrc + tid * 16));
        asm volatile("cp.async.ca.shared.global [%0], [%1], 16;"
                     :: "r"(dst0 + 4096 + tid * 16), "l"(bsrc + tid * 16));
        asm volatile("cp.async.commit_group;");
    };

    float4 acc[4][4];
#pragma unroll
    for (int i = 0; i < 4; i++)
#pragma unroll
        for (int j = 0; j < 4; j++) acc[i][j] = make_float4(0.f, 0.f, 0.f, 0.f);

    const int wm = (warp >> 2) * 4;   // A m-tile base (of 8)
    const int wn = (warp & 3) * 4;    // B n-tile base (of 16)

    auto do_chunk = [&](int kc) {
        const char* st = smem + (kc % 6) * 8192;
        uint4 ah[4];
        uint2 bh[4];
#pragma unroll
        for (int mt = 0; mt < 4; mt++)
            ah[mt] = *(const uint4*)(st + (wm + mt) * 512 + lane * 16);
#pragma unroll
        for (int nt = 0; nt < 4; nt++)
            bh[nt] = *(const uint2*)(st + 4096 + (wn + nt) * 256 + lane * 8);
#pragma unroll
        for (int mt = 0; mt < 4; mt++)
#pragma unroll
            for (int nt = 0; nt < 4; nt++) mma16(acc[mt][nt], ah[mt], bh[nt]);
    };

    issue(0); issue(1); issue(2); issue(3);
#pragma unroll 1
    for (int kc = 0; kc < NKT; kc += 2) {
        if (kc + 2 >= NKT) asm volatile("cp.async.wait_group 0;" ::: "memory");
        else               asm volatile("cp.async.wait_group 2;" ::: "memory");
        __syncthreads();
        // safe: targets stages (kc-2)%6 and (kc-1)%6, all reads finished pre-barrier
        if (kc + 4 < NKT) issue(kc + 4);
        if (kc + 5 < NKT) issue(kc + 5);
        do_chunk(kc);
        do_chunk(kc + 1);
    }

    // epilogue: d0:(r,c) d1:(r,c+1) d2:(r+8,c) d3:(r+8,c+1); r=lane/4, c=2*(lane%4)
    const int rbase = mb * 128 + (warp >> 2) * 64 + (lane >> 2);
    const int cbase = nb * 128 + (warp & 3) * 32 + (lane & 3) * 2;
#pragma unroll
    for (int mt = 0; mt < 4; mt++) {
#pragma unroll
        for (int nt = 0; nt < 4; nt++) {
            const int r = rbase + mt * 16;
            const int c = cbase + nt * 8;
            float4 d = acc[mt][nt];
            if (Ch) {
                if (c < relu_limit) {
                    d.x = fmaxf(d.x, 0.f); d.y = fmaxf(d.y, 0.f);
                    d.z = fmaxf(d.z, 0.f); d.w = fmaxf(d.w, 0.f);
                }
                *(__half2*)(Ch + (size_t)r * N + c) =
                    __float22half2_rn(make_float2(d.x, d.y));
                *(__half2*)(Ch + (size_t)(r + 8) * N + c) =
                    __float22half2_rn(make_float2(d.z, d.w));
            } else {
                if (bias) {
                    float2 bb = *(const float2*)(bias + c);
                    d.x += bb.x; d.y += bb.y; d.z += bb.x; d.w += bb.y;
                }
                *(float2*)(C + (size_t)r * N + c)       = make_float2(d.x, d.y);
                *(float2*)(C + (size_t)(r + 8) * N + c) = make_float2(d.z, d.w);
            }
        }
    }
}

// ---------------------------------------------------------------------------
// KV partial: grid (96, 7); chunk c covers s in [c*448, c*448+448).
// k,v read as fp16, accumulated in fp32.
// ---------------------------------------------------------------------------
__global__ __launch_bounds__(256) void kv_part()
{
    const int bh = blockIdx.x;
    const int pc = blockIdx.y;
    const int b  = bh / 12;
    const int h  = bh % 12;

    __shared__ float Ks[64][64];
    __shared__ float Vs[64][64];

    const int tid = threadIdx.x;
    const int er  = tid >> 4;
    const int dg  = tid & 15;
    const int sl  = tid >> 2;
    const int ch  = tid & 3;

    float4 acc0 = {0,0,0,0}, acc1 = {0,0,0,0}, acc2 = {0,0,0,0}, acc3 = {0,0,0,0};
    float4 ksum = {0,0,0,0};

    const size_t base_k = (size_t)(b * 3136) * 2304 + 768  + h * 64;
    const size_t base_v = (size_t)(b * 3136) * 2304 + 1536 + h * 64;
    const int s_lo = pc * 448, s_hi = s_lo + 448;

    for (int s0 = s_lo; s0 < s_hi; s0 += 64) {
        const __half* kp = g_qkv + base_k + (size_t)(s0 + sl) * 2304 + ch * 16;
        const __half* vp = g_qkv + base_v + (size_t)(s0 + sl) * 2304 + ch * 16;
#pragma unroll
        for (int c = 0; c < 2; c++) {
            uint4 kr = *(const uint4*)(kp + c * 8);
            uint4 vr = *(const uint4*)(vp + c * 8);
            float2 f;
            f = __half22float2(*(__half2*)&kr.x); Ks[sl][ch*16 + c*8 + 0] = f.x; Ks[sl][ch*16 + c*8 + 1] = f.y;
            f = __half22float2(*(__half2*)&kr.y); Ks[sl][ch*16 + c*8 + 2] = f.x; Ks[sl][ch*16 + c*8 + 3] = f.y;
            f = __half22float2(*(__half2*)&kr.z); Ks[sl][ch*16 + c*8 + 4] = f.x; Ks[sl][ch*16 + c*8 + 5] = f.y;
            f = __half22float2(*(__half2*)&kr.w); Ks[sl][ch*16 + c*8 + 6] = f.x; Ks[sl][ch*16 + c*8 + 7] = f.y;
            f = __half22float2(*(__half2*)&vr.x); Vs[sl][ch*16 + c*8 + 0] = f.x; Vs[sl][ch*16 + c*8 + 1] = f.y;
            f = __half22float2(*(__half2*)&vr.y); Vs[sl][ch*16 + c*8 + 2] = f.x; Vs[sl][ch*16 + c*8 + 3] = f.y;
            f = __half22float2(*(__half2*)&vr.z); Vs[sl][ch*16 + c*8 + 4] = f.x; Vs[sl][ch*16 + c*8 + 5] = f.y;
            f = __half22float2(*(__half2*)&vr.w); Vs[sl][ch*16 + c*8 + 6] = f.x; Vs[sl][ch*16 + c*8 + 7] = f.y;
        }
        __syncthreads();

#pragma unroll 8
        for (int s = 0; s < 64; s++) {
            float4 k4 = *(const float4*)&Ks[s][er * 4];
            float4 v4 = *(const float4*)&Vs[s][dg * 4];
            acc0.x += k4.x * v4.x; acc0.y += k4.x * v4.y; acc0.z += k4.x * v4.z; acc0.w += k4.x * v4.w;
            acc1.x += k4.y * v4.x; acc1.y += k4.y * v4.y; acc1.z += k4.y * v4.z; acc1.w += k4.y * v4.w;
            acc2.x += k4.z * v4.x; acc2.y += k4.z * v4.y; acc2.z += k4.z * v4.z; acc2.w += k4.z * v4.w;
            acc3.x += k4.w * v4.x; acc3.y += k4.w * v4.y; acc3.z += k4.w * v4.z; acc3.w += k4.w * v4.w;
            if (dg == 0) {
                ksum.x += k4.x; ksum.y += k4.y; ksum.z += k4.z; ksum.w += k4.w;
            }
        }
        __syncthreads();
    }

    float* kvp = g_kvp + (size_t)(pc * 96 + bh) * 4096;
    *(float4*)&kvp[(er * 4 + 0) * 64 + dg * 4] = acc0;
    *(float4*)&kvp[(er * 4 + 1) * 64 + dg * 4] = acc1;
    *(float4*)&kvp[(er * 4 + 2) * 64 + dg * 4] = acc2;
    *(float4*)&kvp[(er * 4 + 3) * 64 + dg * 4] = acc3;
    if (dg == 0) *(float4*)&g_ksump[(pc * 96 + bh) * 64 + er * 4] = ksum;
}

// ---------------------------------------------------------------------------
// Reduce 7 partials (fixed order) + emit kv as fp16 hi/lo B-fragments.
// ---------------------------------------------------------------------------
__global__ __launch_bounds__(256) void kv_reduce()
{
    const int bh = blockIdx.x;
    const int tid = threadIdx.x;
    __shared__ float kvb[4096];

#pragma unroll 1
    for (int i = tid * 4; i < 4096; i += 1024) {
        float4 s = make_float4(0.f, 0.f, 0.f, 0.f);
#pragma unroll
        for (int p = 0; p < 7; p++) {
            float4 v = *(const float4*)&g_kvp[(size_t)(p * 96 + bh) * 4096 + i];
            s.x += v.x; s.y += v.y; s.z += v.z; s.w += v.w;
        }
        *(float4*)&kvb[i] = s;
    }
    if (tid < 64) {
        float s = 0.f;
#pragma unroll
        for (int p = 0; p < 7; p++) s += g_ksump[(p * 96 + bh) * 64 + tid];
        g_ksum[bh * 64 + tid] = s;
    }
    __syncthreads();

    // B-frag layout: [part(2)][kc(4)][nt(8)][lane(32)] uint2
    char* dst = (char*)g_kvfrag + (size_t)bh * 16384;
#pragma unroll
    for (int pos = tid; pos < 1024; pos += 256) {
        const int kc = pos >> 8, nt = (pos >> 5) & 7, ln = pos & 31;
        const int e0 = kc * 16 + 2 * (ln & 3);
        const int n  = nt * 8 + (ln >> 2);
        float v0 = kvb[e0 * 64 + n],       v1 = kvb[(e0 + 1) * 64 + n];
        float v2 = kvb[(e0 + 8) * 64 + n], v3 = kvb[(e0 + 9) * 64 + n];
        uint32_t l0, l1;
        uint32_t h0 = split2h(make_float2(v0, v1), l0);
        uint32_t h1 = split2h(make_float2(v2, v3), l1);
        *(uint2*)(dst + pos * 8)        = make_uint2(h0, h1);
        *(uint2*)(dst + 8192 + pos * 8) = make_uint2(l0, l1);
    }
}

// ---------------------------------------------------------------------------
// vo_gemm: per (bh, 64-token tile): out = (q @ kv) * z, z = 1/(q.ksum+eps),
// written directly as fp16 hi fragments into g_a2s.
// ---------------------------------------------------------------------------
__global__ __launch_bounds__(128) void vo_gemm()
{
    const int bh   = blockIdx.x;
    const int tile = blockIdx.y;      // 0..48
    const int b = bh / 12, h = bh % 12;

    __shared__ char bfr[16384];
    __shared__ float ks[64];

    const int tid = threadIdx.x, lane = tid & 31, warp = tid >> 5;
    const uint32_t sb = smem_u32(bfr);

    const char* src = (const char*)g_kvfrag + (size_t)bh * 16384;
#pragma unroll
    for (int i = 0; i < 8; i++) {
        const int c = tid + i * 128;
        asm volatile("cp.async.ca.shared.global [%0], [%1], 16;"
                     :: "r"(sb + c * 16), "l"(src + c * 16));
    }
    asm volatile("cp.async.commit_group;");
    if (tid < 64) ks[tid] = g_ksum[bh * 64 + tid];
    asm volatile("cp.async.wait_group 0;" ::: "memory");
    __syncthreads();

    const int r  = lane >> 2;
    const int c2 = 2 * (lane & 3);
    const size_t tok0 = (size_t)b * 3136 + tile * 64 + warp * 16;
    const __half* qbase = g_qkv + tok0 * 2304 + h * 64;

    uint32_t a[4][4];
    float dr = 0.f, dr8 = 0.f;
#pragma unroll
    for (int kc = 0; kc < 4; kc++) {
        const int e0 = kc * 16 + c2;
        a[kc][0] = *(const uint32_t*)(qbase + (size_t)r * 2304 + e0);
        a[kc][1] = *(const uint32_t*)(qbase + (size_t)(r + 8) * 2304 + e0);
        a[kc][2] = *(const uint32_t*)(qbase + (size_t)r * 2304 + e0 + 8);
        a[kc][3] = *(const uint32_t*)(qbase + (size_t)(r + 8) * 2304 + e0 + 8);
        float2 f0 = __half22float2(*(__half2*)&a[kc][0]);
        float2 f1 = __half22float2(*(__half2*)&a[kc][1]);
        float2 f2 = __half22float2(*(__half2*)&a[kc][2]);
        float2 f3 = __half22float2(*(__half2*)&a[kc][3]);
        dr  += f0.x * ks[e0] + f0.y * ks[e0 + 1] + f2.x * ks[e0 + 8] + f2.y * ks[e0 + 9];
        dr8 += f1.x * ks[e0] + f1.y * ks[e0 + 1] + f3.x * ks[e0 + 8] + f3.y * ks[e0 + 9];
    }
    dr  += __shfl_xor_sync(FULL_MASK, dr, 1);  dr  += __shfl_xor_sync(FULL_MASK, dr, 2);
    dr8 += __shfl_xor_sync(FULL_MASK, dr8, 1); dr8 += __shfl_xor_sync(FULL_MASK, dr8, 2);
    const float zr  = 1.0f / (dr + 1e-4f);
    const float zr8 = 1.0f / (dr8 + 1e-4f);

    float4 acc[8];
#pragma unroll
    for (int nt = 0; nt < 8; nt++) acc[nt] = make_float4(0.f, 0.f, 0.f, 0.f);

#pragma unroll
    for (int part = 0; part < 2; part++) {
#pragma unroll
        for (int kc = 0; kc < 4; kc++) {
            const char* pb = bfr + part * 8192 + kc * 2048;
            uint4 av = make_uint4(a[kc][0], a[kc][1], a[kc][2], a[kc][3]);
#pragma unroll
            for (int nt = 0; nt < 8; nt++) {
                uint2 bb = *(const uint2*)(pb + nt * 256 + lane * 8);
                mma16(acc[nt], av, bb);
            }
        }
    }

    // epilogue: hi-only fragment store into g_a2s
    const int mb = (int)(tok0 >> 7);
    const int mt = ((int)tok0 >> 4) & 7;
    char* abase = (char*)g_a2s;
#pragma unroll
    for (int nt = 0; nt < 8; nt++) {
        const int kt = h * 4 + (nt >> 1);
        char* p = abase + (((size_t)(mb * 48 + kt)) << 12) + mt * 512 + lane * 16 + (nt & 1) * 8;
        *(uint32_t*)p = cvt2h(make_float2(acc[nt].x * zr, acc[nt].y * zr));
        *(uint32_t*)(p + 4) = cvt2h(make_float2(acc[nt].z * zr8, acc[nt].w * zr8));
    }
}

// ---------------------------------------------------------------------------
extern "C" void kernel_launch(void* const* d_in, const int* in_sizes, int n_in,
                              void* d_out, int out_size)
{
    const float* x     = (const float*)d_in[0];
    const float* Wqkv  = (const float*)d_in[1];
    const float* Wproj = (const float*)d_in[2];
    const float* bproj = (const float*)d_in[3];
    float* out = (float*)d_out;

    __half* qkv_p;
    uint4 *a1s, *a2s, *b1s, *b2s;
    cudaGetSymbolAddress((void**)&qkv_p, g_qkv);
    cudaGetSymbolAddress((void**)&a1s, g_a1s);
    cudaGetSymbolAddress((void**)&a2s, g_a2s);
    cudaGetSymbolAddress((void**)&b1s, g_b1s);
    cudaGetSymbolAddress((void**)&b2s, g_b2s);

    // 0) pre-split weights + input into fp16 fragment tiles
    split_b<<<2304 / 8, 256>>>(Wqkv,  b1s, 768);
    split_b<<<768 / 8, 256>>>(Wproj, b2s, 768);
    split_a<<<M_TOK / 16, 256>>>(x, a1s, 768);

    // 1) qkv = x @ Wqkv^T -> fp16 (fused ReLU on q,k cols < 1536)
    gemm_f16<<<dim3(2304 / 128, M_TOK / 128), 256>>>(
        a1s, b1s, nullptr, qkv_p, M_TOK, 2304, 768, nullptr, 1536);

    // 2) kv and k_sum per (b,h): S-split partials + reduce (+ kv frag emit)
    kv_part<<<dim3(96, 7), 256>>>();
    kv_reduce<<<96, 256>>>();

    // 3) out = (q @ kv) * z as tensor-core GEMM -> fp16 hi fragments
    vo_gemm<<<dim3(96, 49), 128>>>();

    // 4) out = attn @ Wproj^T + bproj (fp32 out)
    gemm_f16<<<dim3(768 / 128, M_TOK / 128), 256>>>(
        a2s, b2s, out, nullptr, M_TOK, 768, 768, bproj, 0);
}

// round 16
// speedup vs baseline: 1.1343x; 1.1343x over previous
#include <cuda_runtime.h>
#include <cuda_fp16.h>
#include <cstdint>
#include <cstddef>

#define FULL_MASK 0xFFFFFFFFu

// Problem constants: B=128, N=196, C=768, h=12, e=64, frames=16
// tokens M = 25088 ; b = 8 ; S = 3136 ; bh = 96
static const int M_TOK = 25088;
#define KV_SPLIT 7        // 3136 = 7 * 448, 448 = 7*64 (whole 64-tiles!)

// ---------------------------------------------------------------------------
// Scratch (allocation-free: __device__ globals)
// ---------------------------------------------------------------------------
__device__ __half g_qkv[(size_t)25088 * 2304]; // [tok][3*C] (q|k|v) fp16, q/k ReLU'd
__device__ float g_ksum[96 * 64];               // [bh][e]
__device__ float g_kvp[KV_SPLIT * 96 * 64 * 64];   // S-split partials
__device__ float g_ksump[KV_SPLIT * 96 * 64];
__device__ uint2 g_kvfrag[96 * 2048];           // [bh][part(2)][kc(4)][nt(8)][lane(32)] uint2

// fp16 fragment-ordered tiles (hi only).
// A: [mb][kt][mtile(8)][512B] -> chunk 4KB ; B: [nb][kt][ntile(16)][256B] -> 4KB
__device__ uint4 g_a1s[(25088 / 16) * (768 / 16) * 32];   // 38.5 MB (x)
__device__ uint4 g_a2s[(25088 / 16) * (768 / 16) * 32];   // 38.5 MB (attn, by vo_gemm)
__device__ uint4 g_b1s[(2304 / 8) * (768 / 16) * 16];     // 3.5 MB (Wqkv)
__device__ uint4 g_b2s[(768 / 8) * (768 / 16) * 16];      // 1.2 MB (Wproj)

// ---------------------------------------------------------------------------
__device__ __forceinline__ uint32_t smem_u32(const void* p) {
    uint32_t r;
    asm("{.reg .u64 t; cvta.to.shared.u64 t, %1; cvt.u32.u64 %0, t;}" : "=r"(r) : "l"(p));
    return r;
}

// Split float2 -> hi f16x2 (return) + residual f16x2 (lo). low half = .x
__device__ __forceinline__ uint32_t split2h(float2 v, uint32_t& lo) {
    __half2 h = __float22half2_rn(v);
    float2 back = __half22float2(h);
    __half2 l = __float22half2_rn(make_float2(v.x - back.x, v.y - back.y));
    lo = *(uint32_t*)&l;
    return *(uint32_t*)&h;
}
__device__ __forceinline__ uint32_t cvt2h(float2 v) {
    __half2 h = __float22half2_rn(v);
    return *(uint32_t*)&h;
}

// mma.sync m16n8k16 fp16: d += a*b (row.col, f32 accum)
__device__ __forceinline__ void mma16(float4& d, uint4 a, uint2 b) {
    asm volatile(
        "mma.sync.aligned.m16n8k16.row.col.f32.f16.f16.f32 "
        "{%0,%1,%2,%3}, {%4,%5,%6,%7}, {%8,%9}, {%0,%1,%2,%3};"
        : "+f"(d.x), "+f"(d.y), "+f"(d.z), "+f"(d.w)
        : "r"(a.x), "r"(a.y), "r"(a.z), "r"(a.w), "r"(b.x), "r"(b.y));
}

// ---------------------------------------------------------------------------
// split_a: fp32 [M][K] -> A-frag tiles (hi fp16), m16n8k16 A layout.
// ---------------------------------------------------------------------------
__global__ __launch_bounds__(256) void split_a(const float* __restrict__ src,
                                               uint4* __restrict__ dst, int K)
{
    const int NKT  = K >> 4;
    const int strip = blockIdx.x;
    const int warp = threadIdx.x >> 5, lane = threadIdx.x & 31;
    const int mb = strip >> 3, mt = strip & 7;
    const int c2 = (lane & 3) * 2;
    const float* row0 = src + (size_t)(strip * 16 + (lane >> 2)) * K;
    const float* row1 = row0 + (size_t)8 * K;
    char* base = (char*)dst;

    for (int kt = warp; kt < NKT; kt += 8) {
        const int kb = kt * 16;
        uint32_t h0 = cvt2h(*(const float2*)(row0 + kb + c2));
        uint32_t h1 = cvt2h(*(const float2*)(row1 + kb + c2));
        uint32_t h2 = cvt2h(*(const float2*)(row0 + kb + c2 + 8));
        uint32_t h3 = cvt2h(*(const float2*)(row1 + kb + c2 + 8));
        size_t off = ((size_t)(mb * NKT + kt) << 12) + mt * 512 + lane * 16;
        *(uint4*)(base + off) = make_uint4(h0, h1, h2, h3);
    }
}

// ---------------------------------------------------------------------------
// split_b: fp32 [N][K] -> B-frag tiles (hi fp16), m16n8k16 B layout.
// ---------------------------------------------------------------------------
__global__ __launch_bounds__(256) void split_b(const float* __restrict__ src,
                                               uint4* __restrict__ dst, int K)
{
    const int NKT  = K >> 4;
    const int strip = blockIdx.x;
    const int warp = threadIdx.x >> 5, lane = threadIdx.x & 31;
    const int nb = strip >> 4, nt = strip & 15;
    const int c2 = (lane & 3) * 2;
    const float* row = src + (size_t)(strip * 8 + (lane >> 2)) * K;
    char* base = (char*)dst;

    for (int kt = warp; kt < NKT; kt += 8) {
        const int kb = kt * 16;
        uint32_t h0 = cvt2h(*(const float2*)(row + kb + c2));
        uint32_t h1 = cvt2h(*(const float2*)(row + kb + c2 + 8));
        size_t off = ((size_t)(nb * NKT + kt) << 12) + nt * 256 + lane * 8;
        *(uint2*)(base + off) = make_uint2(h0, h1);
    }
}

// ---------------------------------------------------------------------------
// fp16 1-term HMMA GEMM on pre-split tiles (R13 structure). Paired-chunk loop
// (barrier pair per 2 chunks), 4-stage cp.async.cg ring (L1 bypass),
// 256 threads, 128x128 tile, BK=16, 2 CTAs/SM.
// Output: half (Ch, ReLU<relu_limit) or fp32 (C, +bias).
// ---------------------------------------------------------------------------
__global__ __launch_bounds__(256, 2) void gemm_f16(
    const uint4* __restrict__ As, const uint4* __restrict__ Bs,
    float* __restrict__ C, __half* __restrict__ Ch,
    int M, int N, int K, const float* __restrict__ bias, int relu_limit)
{
    __shared__ char smem[4 * 8192];

    const int tid  = threadIdx.x;
    const int lane = tid & 31;
    const int warp = tid >> 5;
    const int mb   = blockIdx.y;
    const int nb   = blockIdx.x;
    const int NKT  = K >> 4;          // 48 (even)
    const uint32_t sb = smem_u32(smem);

    const char* Abase = (const char*)As + ((size_t)mb * NKT << 12);
    const char* Bbase = (const char*)Bs + ((size_t)nb * NKT << 12);

    auto issue = [&](int kc) {
        const char* asrc = Abase + ((size_t)kc << 12);
        const char* bsrc = Bbase + ((size_t)kc << 12);
        const uint32_t dst0 = sb + (kc & 3) * 8192;
        asm volatile("cp.async.cg.shared.global [%0], [%1], 16;"
                     :: "r"(dst0 + tid * 16), "l"(asrc + tid * 16));
        asm volatile("cp.async.cg.shared.global [%0], [%1], 16;"
                     :: "r"(dst0 + 4096 + tid * 16), "l"(bsrc + tid * 16));
        asm volatile("cp.async.commit_group;");
    };

    float4 acc[4][4];
#pragma unroll
    for (int i = 0; i < 4; i++)
#pragma unroll
        for (int j = 0; j < 4; j++) acc[i][j] = make_float4(0.f, 0.f, 0.f, 0.f);

    const int wm = (warp >> 2) * 4;   // A m-tile base (of 8)
    const int wn = (warp & 3) * 4;    // B n-tile base (of 16)

    auto do_chunk = [&](int kc) {
        const char* st = smem + (kc & 3) * 8192;
        uint4 ah[4];
        uint2 bh[4];
#pragma unroll
        for (int mt = 0; mt < 4; mt++)
            ah[mt] = *(const uint4*)(st + (wm + mt) * 512 + lane * 16);
#pragma unroll
        for (int nt = 0; nt < 4; nt++)
            bh[nt] = *(const uint2*)(st + 4096 + (wn + nt) * 256 + lane * 8);
#pragma unroll
        for (int mt = 0; mt < 4; mt++)
#pragma unroll
            for (int nt = 0; nt < 4; nt++) mma16(acc[mt][nt], ah[mt], bh[nt]);
    };

    issue(0); issue(1); issue(2); issue(3);
#pragma unroll 1
    for (int kc = 0; kc < NKT; kc += 2) {
        if (kc + 2 >= NKT) asm volatile("cp.async.wait_group 0;" ::: "memory");
        else               asm volatile("cp.async.wait_group 2;" ::: "memory");
        __syncthreads();
        do_chunk(kc);
        do_chunk(kc + 1);
        __syncthreads();
        if (kc + 4 < NKT) issue(kc + 4);
        if (kc + 5 < NKT) issue(kc + 5);
    }

    // epilogue: d0:(r,c) d1:(r,c+1) d2:(r+8,c) d3:(r+8,c+1); r=lane/4, c=2*(lane%4)
    const int rbase = mb * 128 + (warp >> 2) * 64 + (lane >> 2);
    const int cbase = nb * 128 + (warp & 3) * 32 + (lane & 3) * 2;
#pragma unroll
    for (int mt = 0; mt < 4; mt++) {
#pragma unroll
        for (int nt = 0; nt < 4; nt++) {
            const int r = rbase + mt * 16;
            const int c = cbase + nt * 8;
            float4 d = acc[mt][nt];
            if (Ch) {
                if (c < relu_limit) {
                    d.x = fmaxf(d.x, 0.f); d.y = fmaxf(d.y, 0.f);
                    d.z = fmaxf(d.z, 0.f); d.w = fmaxf(d.w, 0.f);
                }
                *(__half2*)(Ch + (size_t)r * N + c) =
                    __float22half2_rn(make_float2(d.x, d.y));
                *(__half2*)(Ch + (size_t)(r + 8) * N + c) =
                    __float22half2_rn(make_float2(d.z, d.w));
            } else {
                if (bias) {
                    float2 bb = *(const float2*)(bias + c);
                    d.x += bb.x; d.y += bb.y; d.z += bb.x; d.w += bb.y;
                }
                *(float2*)(C + (size_t)r * N + c)       = make_float2(d.x, d.y);
                *(float2*)(C + (size_t)(r + 8) * N + c) = make_float2(d.z, d.w);
            }
        }
    }
}

// ---------------------------------------------------------------------------
// KV partial: grid (96, KV_SPLIT); chunk c covers s in [c*448, c*448+448).
// 448 = 7 whole 64-tiles (exact — no overlap). k,v fp16 in, fp32 accum.
// ---------------------------------------------------------------------------
__global__ __launch_bounds__(256) void kv_part()
{
    const int bh = blockIdx.x;
    const int pc = blockIdx.y;
    const int b  = bh / 12;
    const int h  = bh % 12;

    __shared__ float Ks[64][64];
    __shared__ float Vs[64][64];

    const int tid = threadIdx.x;
    const int er  = tid >> 4;
    const int dg  = tid & 15;
    const int sl  = tid >> 2;
    const int ch  = tid & 3;

    float4 acc0 = {0,0,0,0}, acc1 = {0,0,0,0}, acc2 = {0,0,0,0}, acc3 = {0,0,0,0};
    float4 ksum = {0,0,0,0};

    const size_t base_k = (size_t)(b * 3136) * 2304 + 768  + h * 64;
    const size_t base_v = (size_t)(b * 3136) * 2304 + 1536 + h * 64;
    const int s_lo = pc * 448, s_hi = s_lo + 448;

    for (int s0 = s_lo; s0 < s_hi; s0 += 64) {
        const __half* kp = g_qkv + base_k + (size_t)(s0 + sl) * 2304 + ch * 16;
        const __half* vp = g_qkv + base_v + (size_t)(s0 + sl) * 2304 + ch * 16;
#pragma unroll
        for (int c = 0; c < 2; c++) {
            uint4 kr = *(const uint4*)(kp + c * 8);
            uint4 vr = *(const uint4*)(vp + c * 8);
            float2 f;
            f = __half22float2(*(__half2*)&kr.x); Ks[sl][ch*16 + c*8 + 0] = f.x; Ks[sl][ch*16 + c*8 + 1] = f.y;
            f = __half22float2(*(__half2*)&kr.y); Ks[sl][ch*16 + c*8 + 2] = f.x; Ks[sl][ch*16 + c*8 + 3] = f.y;
            f = __half22float2(*(__half2*)&kr.z); Ks[sl][ch*16 + c*8 + 4] = f.x; Ks[sl][ch*16 + c*8 + 5] = f.y;
            f = __half22float2(*(__half2*)&kr.w); Ks[sl][ch*16 + c*8 + 6] = f.x; Ks[sl][ch*16 + c*8 + 7] = f.y;
            f = __half22float2(*(__half2*)&vr.x); Vs[sl][ch*16 + c*8 + 0] = f.x; Vs[sl][ch*16 + c*8 + 1] = f.y;
            f = __half22float2(*(__half2*)&vr.y); Vs[sl][ch*16 + c*8 + 2] = f.x; Vs[sl][ch*16 + c*8 + 3] = f.y;
            f = __half22float2(*(__half2*)&vr.z); Vs[sl][ch*16 + c*8 + 4] = f.x; Vs[sl][ch*16 + c*8 + 5] = f.y;
            f = __half22float2(*(__half2*)&vr.w); Vs[sl][ch*16 + c*8 + 6] = f.x; Vs[sl][ch*16 + c*8 + 7] = f.y;
        }
        __syncthreads();

#pragma unroll 8
        for (int s = 0; s < 64; s++) {
            float4 k4 = *(const float4*)&Ks[s][er * 4];
            float4 v4 = *(const float4*)&Vs[s][dg * 4];
            acc0.x += k4.x * v4.x; acc0.y += k4.x * v4.y; acc0.z += k4.x * v4.z; acc0.w += k4.x * v4.w;
            acc1.x += k4.y * v4.x; acc1.y += k4.y * v4.y; acc1.z += k4.y * v4.z; acc1.w += k4.y * v4.w;
            acc2.x += k4.z * v4.x; acc2.y += k4.z * v4.y; acc2.z += k4.z * v4.z; acc2.w += k4.z * v4.w;
            acc3.x += k4.w * v4.x; acc3.y += k4.w * v4.y; acc3.z += k4.w * v4.z; acc3.w += k4.w * v4.w;
            if (dg == 0) {
                ksum.x += k4.x; ksum.y += k4.y; ksum.z += k4.z; ksum.w += k4.w;
            }
        }
        __syncthreads();
    }

    float* kvp = g_kvp + (size_t)(pc * 96 + bh) * 4096;
    *(float4*)&kvp[(er * 4 + 0) * 64 + dg * 4] = acc0;
    *(float4*)&kvp[(er * 4 + 1) * 64 + dg * 4] = acc1;
    *(float4*)&kvp[(er * 4 + 2) * 64 + dg * 4] = acc2;
    *(float4*)&kvp[(er * 4 + 3) * 64 + dg * 4] = acc3;
    if (dg == 0) *(float4*)&g_ksump[(pc * 96 + bh) * 64 + er * 4] = ksum;
}

// ---------------------------------------------------------------------------
// Reduce KV_SPLIT partials (fixed order) + emit kv as fp16 hi/lo B-fragments.
// ---------------------------------------------------------------------------
__global__ __launch_bounds__(256) void kv_reduce()
{
    const int bh = blockIdx.x;
    const int tid = threadIdx.x;
    __shared__ float kvb[4096];

#pragma unroll 1
    for (int i = tid * 4; i < 4096; i += 1024) {
        float4 s = make_float4(0.f, 0.f, 0.f, 0.f);
#pragma unroll
        for (int p = 0; p < KV_SPLIT; p++) {
            float4 v = *(const float4*)&g_kvp[(size_t)(p * 96 + bh) * 4096 + i];
            s.x += v.x; s.y += v.y; s.z += v.z; s.w += v.w;
        }
        *(float4*)&kvb[i] = s;
    }
    if (tid < 64) {
        float s = 0.f;
#pragma unroll
        for (int p = 0; p < KV_SPLIT; p++) s += g_ksump[(p * 96 + bh) * 64 + tid];
        g_ksum[bh * 64 + tid] = s;
    }
    __syncthreads();

    // B-frag layout: [part(2)][kc(4)][nt(8)][lane(32)] uint2
    char* dst = (char*)g_kvfrag + (size_t)bh * 16384;
#pragma unroll
    for (int pos = tid; pos < 1024; pos += 256) {
        const int kc = pos >> 8, nt = (pos >> 5) & 7, ln = pos & 31;
        const int e0 = kc * 16 + 2 * (ln & 3);
        const int n  = nt * 8 + (ln >> 2);
        float v0 = kvb[e0 * 64 + n],       v1 = kvb[(e0 + 1) * 64 + n];
        float v2 = kvb[(e0 + 8) * 64 + n], v3 = kvb[(e0 + 9) * 64 + n];
        uint32_t l0, l1;
        uint32_t h0 = split2h(make_float2(v0, v1), l0);
        uint32_t h1 = split2h(make_float2(v2, v3), l1);
        *(uint2*)(dst + pos * 8)        = make_uint2(h0, h1);
        *(uint2*)(dst + 8192 + pos * 8) = make_uint2(l0, l1);
    }
}

// ---------------------------------------------------------------------------
// vo_gemm: per (bh, 64-token tile): out = (q @ kv) * z, z = 1/(q.ksum+eps),
// written directly as fp16 hi fragments into g_a2s.
// ---------------------------------------------------------------------------
__global__ __launch_bounds__(128) void vo_gemm()
{
    const int bh   = blockIdx.x;
    const int tile = blockIdx.y;      // 0..48
    const int b = bh / 12, h = bh % 12;

    __shared__ char bfr[16384];
    __shared__ float ks[64];

    const int tid = threadIdx.x, lane = tid & 31, warp = tid >> 5;
    const uint32_t sb = smem_u32(bfr);

    const char* src = (const char*)g_kvfrag + (size_t)bh * 16384;
#pragma unroll
    for (int i = 0; i < 8; i++) {
        const int c = tid + i * 128;
        asm volatile("cp.async.cg.shared.global [%0], [%1], 16;"
                     :: "r"(sb + c * 16), "l"(src + c * 16));
    }
    asm volatile("cp.async.commit_group;");
    if (tid < 64) ks[tid] = g_ksum[bh * 64 + tid];
    asm volatile("cp.async.wait_group 0;" ::: "memory");
    __syncthreads();

    const int r  = lane >> 2;
    const int c2 = 2 * (lane & 3);
    const size_t tok0 = (size_t)b * 3136 + tile * 64 + warp * 16;
    const __half* qbase = g_qkv + tok0 * 2304 + h * 64;

    uint32_t a[4][4];
    float dr = 0.f, dr8 = 0.f;
#pragma unroll
    for (int kc = 0; kc < 4; kc++) {
        const int e0 = kc * 16 + c2;
        a[kc][0] = *(const uint32_t*)(qbase + (size_t)r * 2304 + e0);
        a[kc][1] = *(const uint32_t*)(qbase + (size_t)(r + 8) * 2304 + e0);
        a[kc][2] = *(const uint32_t*)(qbase + (size_t)r * 2304 + e0 + 8);
        a[kc][3] = *(const uint32_t*)(qbase + (size_t)(r + 8) * 2304 + e0 + 8);
        float2 f0 = __half22float2(*(__half2*)&a[kc][0]);
        float2 f1 = __half22float2(*(__half2*)&a[kc][1]);
        float2 f2 = __half22float2(*(__half2*)&a[kc][2]);
        float2 f3 = __half22float2(*(__half2*)&a[kc][3]);
        dr  += f0.x * ks[e0] + f0.y * ks[e0 + 1] + f2.x * ks[e0 + 8] + f2.y * ks[e0 + 9];
        dr8 += f1.x * ks[e0] + f1.y * ks[e0 + 1] + f3.x * ks[e0 + 8] + f3.y * ks[e0 + 9];
    }
    dr  += __shfl_xor_sync(FULL_MASK, dr, 1);  dr  += __shfl_xor_sync(FULL_MASK, dr, 2);
    dr8 += __shfl_xor_sync(FULL_MASK, dr8, 1); dr8 += __shfl_xor_sync(FULL_MASK, dr8, 2);
    const float zr  = 1.0f / (dr + 1e-4f);
    const float zr8 = 1.0f / (dr8 + 1e-4f);

    float4 acc[8];
#pragma unroll
    for (int nt = 0; nt < 8; nt++) acc[nt] = make_float4(0.f, 0.f, 0.f, 0.f);

#pragma unroll
    for (int part = 0; part < 2; part++) {
#pragma unroll
        for (int kc = 0; kc < 4; kc++) {
            const char* pb = bfr + part * 8192 + kc * 2048;
            uint4 av = make_uint4(a[kc][0], a[kc][1], a[kc][2], a[kc][3]);
#pragma unroll
            for (int nt = 0; nt < 8; nt++) {
                uint2 bb = *(const uint2*)(pb + nt * 256 + lane * 8);
                mma16(acc[nt], av, bb);
            }
        }
    }

    // epilogue: hi-only fragment store into g_a2s
    const int mb = (int)(tok0 >> 7);
    const int mt = ((int)tok0 >> 4) & 7;
    char* abase = (char*)g_a2s;
#pragma unroll
    for (int nt = 0; nt < 8; nt++) {
        const int kt = h * 4 + (nt >> 1);
        char* p = abase + (((size_t)(mb * 48 + kt)) << 12) + mt * 512 + lane * 16 + (nt & 1) * 8;
        *(uint32_t*)p = cvt2h(make_float2(acc[nt].x * zr, acc[nt].y * zr));
        *(uint32_t*)(p + 4) = cvt2h(make_float2(acc[nt].z * zr8, acc[nt].w * zr8));
    }
}

// ---------------------------------------------------------------------------
extern "C" void kernel_launch(void* const* d_in, const int* in_sizes, int n_in,
                              void* d_out, int out_size)
{
    const float* x     = (const float*)d_in[0];
    const float* Wqkv  = (const float*)d_in[1];
    const float* Wproj = (const float*)d_in[2];
    const float* bproj = (const float*)d_in[3];
    float* out = (float*)d_out;

    __half* qkv_p;
    uint4 *a1s, *a2s, *b1s, *b2s;
    cudaGetSymbolAddress((void**)&qkv_p, g_qkv);
    cudaGetSymbolAddress((void**)&a1s, g_a1s);
    cudaGetSymbolAddress((void**)&a2s, g_a2s);
    cudaGetSymbolAddress((void**)&b1s, g_b1s);
    cudaGetSymbolAddress((void**)&b2s, g_b2s);

    // 0) pre-split weights + input into fp16 fragment tiles
    split_b<<<2304 / 8, 256>>>(Wqkv,  b1s, 768);
    split_b<<<768 / 8, 256>>>(Wproj, b2s, 768);
    split_a<<<M_TOK / 16, 256>>>(x, a1s, 768);

    // 1) qkv = x @ Wqkv^T -> fp16 (fused ReLU on q,k cols < 1536)
    gemm_f16<<<dim3(2304 / 128, M_TOK / 128), 256>>>(
        a1s, b1s, nullptr, qkv_p, M_TOK, 2304, 768, nullptr, 1536);

    // 2) kv and k_sum per (b,h): S-split partials + reduce (+ kv frag emit)
    kv_part<<<dim3(96, KV_SPLIT), 256>>>();
    kv_reduce<<<96, 256>>>();

    // 3) out = (q @ kv) * z as tensor-core GEMM -> fp16 hi fragments
    vo_gemm<<<dim3(96, 49), 128>>>();

    // 4) out = attn @ Wproj^T + bproj (fp32 out)
    gemm_f16<<<dim3(768 / 128, M_TOK / 128), 256>>>(
        a2s, b2s, out, nullptr, M_TOK, 768, 768, bproj, 0);
}

// round 17
// speedup vs baseline: 1.2306x; 1.0849x over previous
#include <cuda_runtime.h>
#include <cuda_fp16.h>
#include <cstdint>
#include <cstddef>

#define FULL_MASK 0xFFFFFFFFu

// Problem constants: B=128, N=196, C=768, h=12, e=64, frames=16
// tokens M = 25088 ; b = 8 ; S = 3136 ; bh = 96
static const int M_TOK = 25088;
#define KV_SPLIT 7        // 3136 = 7 * 448, 448 = 7*64 (whole 64-tiles)

// ---------------------------------------------------------------------------
// Scratch (allocation-free: __device__ globals)
// ---------------------------------------------------------------------------
__device__ __half g_qkv[(size_t)25088 * 2304]; // [tok][3*C] (q|k|v) fp16, q/k ReLU'd
__device__ float g_ksum[96 * 64];               // [bh][e]
__device__ float g_kvp[KV_SPLIT * 96 * 64 * 64];   // S-split partials
__device__ float g_ksump[KV_SPLIT * 96 * 64];
__device__ uint2 g_kvfrag[96 * 2048];           // [bh][part(2)][kc(4)][nt(8)][lane(32)] uint2

// fp16 fragment-ordered tiles (hi only).
// A: [mb][kt][mtile(8)][512B] -> chunk 4KB ; B: [nb][kt][ntile(16)][256B] -> 4KB
__device__ uint4 g_a1s[(25088 / 16) * (768 / 16) * 32];   // 38.5 MB (x)
__device__ uint4 g_a2s[(25088 / 16) * (768 / 16) * 32];   // 38.5 MB (attn, by vo_gemm)
__device__ uint4 g_b1s[(2304 / 8) * (768 / 16) * 16];     // 3.5 MB (Wqkv)
__device__ uint4 g_b2s[(768 / 8) * (768 / 16) * 16];      // 1.2 MB (Wproj)

// ---------------------------------------------------------------------------
__device__ __forceinline__ uint32_t smem_u32(const void* p) {
    uint32_t r;
    asm("{.reg .u64 t; cvta.to.shared.u64 t, %1; cvt.u32.u64 %0, t;}" : "=r"(r) : "l"(p));
    return r;
}

// Split float2 -> hi f16x2 (return) + residual f16x2 (lo). low half = .x
__device__ __forceinline__ uint32_t split2h(float2 v, uint32_t& lo) {
    __half2 h = __float22half2_rn(v);
    float2 back = __half22float2(h);
    __half2 l = __float22half2_rn(make_float2(v.x - back.x, v.y - back.y));
    lo = *(uint32_t*)&l;
    return *(uint32_t*)&h;
}
__device__ __forceinline__ uint32_t cvt2h(float2 v) {
    __half2 h = __float22half2_rn(v);
    return *(uint32_t*)&h;
}

// mma.sync m16n8k16 fp16: d += a*b (row.col, f32 accum)
__device__ __forceinline__ void mma16(float4& d, uint4 a, uint2 b) {
    asm volatile(
        "mma.sync.aligned.m16n8k16.row.col.f32.f16.f16.f32 "
        "{%0,%1,%2,%3}, {%4,%5,%6,%7}, {%8,%9}, {%0,%1,%2,%3};"
        : "+f"(d.x), "+f"(d.y), "+f"(d.z), "+f"(d.w)
        : "r"(a.x), "r"(a.y), "r"(a.z), "r"(a.w), "r"(b.x), "r"(b.y));
}

// ---------------------------------------------------------------------------
// split_a: fp32 [M][K] -> A-frag tiles (hi fp16), m16n8k16 A layout.
// ---------------------------------------------------------------------------
__global__ __launch_bounds__(256) void split_a(const float* __restrict__ src,
                                               uint4* __restrict__ dst, int K)
{
    const int NKT  = K >> 4;
    const int strip = blockIdx.x;
    const int warp = threadIdx.x >> 5, lane = threadIdx.x & 31;
    const int mb = strip >> 3, mt = strip & 7;
    const int c2 = (lane & 3) * 2;
    const float* row0 = src + (size_t)(strip * 16 + (lane >> 2)) * K;
    const float* row1 = row0 + (size_t)8 * K;
    char* base = (char*)dst;

    for (int kt = warp; kt < NKT; kt += 8) {
        const int kb = kt * 16;
        uint32_t h0 = cvt2h(*(const float2*)(row0 + kb + c2));
        uint32_t h1 = cvt2h(*(const float2*)(row1 + kb + c2));
        uint32_t h2 = cvt2h(*(const float2*)(row0 + kb + c2 + 8));
        uint32_t h3 = cvt2h(*(const float2*)(row1 + kb + c2 + 8));
        size_t off = ((size_t)(mb * NKT + kt) << 12) + mt * 512 + lane * 16;
        *(uint4*)(base + off) = make_uint4(h0, h1, h2, h3);
    }
}

// ---------------------------------------------------------------------------
// split_b: fp32 [N][K] -> B-frag tiles (hi fp16), m16n8k16 B layout.
// ---------------------------------------------------------------------------
__global__ __launch_bounds__(256) void split_b(const float* __restrict__ src,
                                               uint4* __restrict__ dst, int K)
{
    const int NKT  = K >> 4;
    const int strip = blockIdx.x;
    const int warp = threadIdx.x >> 5, lane = threadIdx.x & 31;
    const int nb = strip >> 4, nt = strip & 15;
    const int c2 = (lane & 3) * 2;
    const float* row = src + (size_t)(strip * 8 + (lane >> 2)) * K;
    char* base = (char*)dst;

    for (int kt = warp; kt < NKT; kt += 8) {
        const int kb = kt * 16;
        uint32_t h0 = cvt2h(*(const float2*)(row + kb + c2));
        uint32_t h1 = cvt2h(*(const float2*)(row + kb + c2 + 8));
        size_t off = ((size_t)(nb * NKT + kt) << 12) + nt * 256 + lane * 8;
        *(uint2*)(base + off) = make_uint2(h0, h1);
    }
}

// ---------------------------------------------------------------------------
// fp16 1-term HMMA GEMM on pre-split tiles. Paired-chunk loop, 4-stage
// cp.async.cg ring (L1 bypass), 256 threads, 128x128 tile, BK=16, 2 CTAs/SM.
// Output: half (Ch, ReLU<relu_limit) or fp32 (C, +bias).
// ---------------------------------------------------------------------------
__global__ __launch_bounds__(256, 2) void gemm_f16(
    const uint4* __restrict__ As, const uint4* __restrict__ Bs,
    float* __restrict__ C, __half* __restrict__ Ch,
    int M, int N, int K, const float* __restrict__ bias, int relu_limit)
{
    __shared__ char smem[4 * 8192];

    const int tid  = threadIdx.x;
    const int lane = tid & 31;
    const int warp = tid >> 5;
    const int mb   = blockIdx.y;
    const int nb   = blockIdx.x;
    const int NKT  = K >> 4;          // 48 (even)
    const uint32_t sb = smem_u32(smem);

    const char* Abase = (const char*)As + ((size_t)mb * NKT << 12);
    const char* Bbase = (const char*)Bs + ((size_t)nb * NKT << 12);

    auto issue = [&](int kc) {
        const char* asrc = Abase + ((size_t)kc << 12);
        const char* bsrc = Bbase + ((size_t)kc << 12);
        const uint32_t dst0 = sb + (kc & 3) * 8192;
        asm volatile("cp.async.cg.shared.global [%0], [%1], 16;"
                     :: "r"(dst0 + tid * 16), "l"(asrc + tid * 16));
        asm volatile("cp.async.cg.shared.global [%0], [%1], 16;"
                     :: "r"(dst0 + 4096 + tid * 16), "l"(bsrc + tid * 16));
        asm volatile("cp.async.commit_group;");
    };

    float4 acc[4][4];
#pragma unroll
    for (int i = 0; i < 4; i++)
#pragma unroll
        for (int j = 0; j < 4; j++) acc[i][j] = make_float4(0.f, 0.f, 0.f, 0.f);

    const int wm = (warp >> 2) * 4;   // A m-tile base (of 8)
    const int wn = (warp & 3) * 4;    // B n-tile base (of 16)

    auto do_chunk = [&](int kc) {
        const char* st = smem + (kc & 3) * 8192;
        uint4 ah[4];
        uint2 bh[4];
#pragma unroll
        for (int mt = 0; mt < 4; mt++)
            ah[mt] = *(const uint4*)(st + (wm + mt) * 512 + lane * 16);
#pragma unroll
        for (int nt = 0; nt < 4; nt++)
            bh[nt] = *(const uint2*)(st + 4096 + (wn + nt) * 256 + lane * 8);
#pragma unroll
        for (int mt = 0; mt < 4; mt++)
#pragma unroll
            for (int nt = 0; nt < 4; nt++) mma16(acc[mt][nt], ah[mt], bh[nt]);
    };

    issue(0); issue(1); issue(2); issue(3);
#pragma unroll 1
    for (int kc = 0; kc < NKT; kc += 2) {
        if (kc + 2 >= NKT) asm volatile("cp.async.wait_group 0;" ::: "memory");
        else               asm volatile("cp.async.wait_group 2;" ::: "memory");
        __syncthreads();
        do_chunk(kc);
        do_chunk(kc + 1);
        __syncthreads();
        if (kc + 4 < NKT) issue(kc + 4);
        if (kc + 5 < NKT) issue(kc + 5);
    }

    // epilogue: d0:(r,c) d1:(r,c+1) d2:(r+8,c) d3:(r+8,c+1); r=lane/4, c=2*(lane%4)
    const int rbase = mb * 128 + (warp >> 2) * 64 + (lane >> 2);
    const int cbase = nb * 128 + (warp & 3) * 32 + (lane & 3) * 2;
#pragma unroll
    for (int mt = 0; mt < 4; mt++) {
#pragma unroll
        for (int nt = 0; nt < 4; nt++) {
            const int r = rbase + mt * 16;
            const int c = cbase + nt * 8;
            float4 d = acc[mt][nt];
            if (Ch) {
                if (c < relu_limit) {
                    d.x = fmaxf(d.x, 0.f); d.y = fmaxf(d.y, 0.f);
                    d.z = fmaxf(d.z, 0.f); d.w = fmaxf(d.w, 0.f);
                }
                *(__half2*)(Ch + (size_t)r * N + c) =
                    __float22half2_rn(make_float2(d.x, d.y));
                *(__half2*)(Ch + (size_t)(r + 8) * N + c) =
                    __float22half2_rn(make_float2(d.z, d.w));
            } else {
                if (bias) {
                    float2 bb = *(const float2*)(bias + c);
                    d.x += bb.x; d.y += bb.y; d.z += bb.x; d.w += bb.y;
                }
                *(float2*)(C + (size_t)r * N + c)       = make_float2(d.x, d.y);
                *(float2*)(C + (size_t)(r + 8) * N + c) = make_float2(d.z, d.w);
            }
        }
    }
}

// ---------------------------------------------------------------------------
// KV partial (HMMA): grid (96, KV_SPLIT); chunk covers 448 s (7 x 64-tiles).
// kv[e][d] = sum_s k[s][e]*v[s][d]: per tile, k/v loaded TRANSPOSED into
// smem (KT[e][s], VT[d][s], stride 66 halves), fragments via plain LDS.
// Warp w: e-tile = w>>1 (m16), d-half = w&1 (4 n8-tiles).
// ksum accumulated from KT by all threads, smem-reduced.
// ---------------------------------------------------------------------------
#define KVT_STRIDE 66
__global__ __launch_bounds__(256) void kv_part()
{
    const int bh = blockIdx.x;
    const int pc = blockIdx.y;
    const int b  = bh / 12;
    const int h  = bh % 12;

    __shared__ __half KT[64 * KVT_STRIDE];
    __shared__ __half VT[64 * KVT_STRIDE];
    __shared__ float red[256];

    const int tid  = threadIdx.x;
    const int lane = tid & 31;
    const int warp = tid >> 5;
    const int sl   = tid >> 2;     // loader s-row 0..63
    const int ch   = tid & 3;      // loader e-range ch*16
    const int r    = lane >> 2;    // frag row
    const int c2   = 2 * (lane & 3);

    const int etile = warp >> 1;          // 0..3  (m16 rows e = etile*16..)
    const int nbase = (warp & 1) * 4;     // n8-tiles nbase..nbase+3 (d cols)

    const size_t base_k = (size_t)(b * 3136) * 2304 + 768  + h * 64;
    const size_t base_v = (size_t)(b * 3136) * 2304 + 1536 + h * 64;
    const int s_lo = pc * 448;

    float4 acc[4];
#pragma unroll
    for (int nt = 0; nt < 4; nt++) acc[nt] = make_float4(0.f, 0.f, 0.f, 0.f);
    float kacc = 0.f;

    const int se = tid & 63;   // ksum: e index
    const int sq = tid >> 6;   // ksum: s quarter

#pragma unroll 1
    for (int t = 0; t < 7; t++) {
        const int s0 = s_lo + t * 64;
        const __half* kp = g_qkv + base_k + (size_t)(s0 + sl) * 2304 + ch * 16;
        const __half* vp = g_qkv + base_v + (size_t)(s0 + sl) * 2304 + ch * 16;
        uint4 kr0 = *(const uint4*)kp;
        uint4 kr1 = *(const uint4*)(kp + 8);
        uint4 vr0 = *(const uint4*)vp;
        uint4 vr1 = *(const uint4*)(vp + 8);
        const __half* kv0 = (const __half*)&kr0;
        const __half* kv1 = (const __half*)&kr1;
        const __half* vv0 = (const __half*)&vr0;
        const __half* vv1 = (const __half*)&vr1;
#pragma unroll
        for (int j = 0; j < 8; j++) {
            KT[(ch * 16 + j) * KVT_STRIDE + sl]     = kv0[j];
            KT[(ch * 16 + 8 + j) * KVT_STRIDE + sl] = kv1[j];
            VT[(ch * 16 + j) * KVT_STRIDE + sl]     = vv0[j];
            VT[(ch * 16 + 8 + j) * KVT_STRIDE + sl] = vv1[j];
        }
        __syncthreads();

        // ksum partials: thread sums KT[se][sq*16 .. sq*16+15]
#pragma unroll
        for (int j = 0; j < 16; j++)
            kacc += __half2float(KT[se * KVT_STRIDE + sq * 16 + j]);

        // HMMA: 4 s-chunks x 4 n-tiles
#pragma unroll
        for (int kc = 0; kc < 4; kc++) {
            const int sc = kc * 16;
            uint4 a;
            a.x = *(const uint32_t*)&KT[(etile * 16 + r) * KVT_STRIDE + sc + c2];
            a.y = *(const uint32_t*)&KT[(etile * 16 + r + 8) * KVT_STRIDE + sc + c2];
            a.z = *(const uint32_t*)&KT[(etile * 16 + r) * KVT_STRIDE + sc + c2 + 8];
            a.w = *(const uint32_t*)&KT[(etile * 16 + r + 8) * KVT_STRIDE + sc + c2 + 8];
#pragma unroll
            for (int nt = 0; nt < 4; nt++) {
                const int drow = (nbase + nt) * 8 + r;
                uint2 bb;
                bb.x = *(const uint32_t*)&VT[drow * KVT_STRIDE + sc + c2];
                bb.y = *(const uint32_t*)&VT[drow * KVT_STRIDE + sc + c2 + 8];
                mma16(acc[nt], a, bb);
            }
        }
        __syncthreads();
    }

    // epilogue: kv partial [e][d]
    float* kvp = g_kvp + (size_t)(pc * 96 + bh) * 4096;
    const int e0 = etile * 16 + r;
#pragma unroll
    for (int nt = 0; nt < 4; nt++) {
        const int c = (nbase + nt) * 8 + c2;
        *(float2*)&kvp[e0 * 64 + c]       = make_float2(acc[nt].x, acc[nt].y);
        *(float2*)&kvp[(e0 + 8) * 64 + c] = make_float2(acc[nt].z, acc[nt].w);
    }

    // ksum reduce (4 partials per e)
    red[tid] = kacc;
    __syncthreads();
    if (tid < 64) {
        float s = red[tid] + red[tid + 64] + red[tid + 128] + red[tid + 192];
        g_ksump[(pc * 96 + bh) * 64 + tid] = s;
    }
}

// ---------------------------------------------------------------------------
// Reduce KV_SPLIT partials (fixed order) + emit kv as fp16 hi/lo B-fragments.
// ---------------------------------------------------------------------------
__global__ __launch_bounds__(256) void kv_reduce()
{
    const int bh = blockIdx.x;
    const int tid = threadIdx.x;
    __shared__ float kvb[4096];

#pragma unroll 1
    for (int i = tid * 4; i < 4096; i += 1024) {
        float4 s = make_float4(0.f, 0.f, 0.f, 0.f);
#pragma unroll
        for (int p = 0; p < KV_SPLIT; p++) {
            float4 v = *(const float4*)&g_kvp[(size_t)(p * 96 + bh) * 4096 + i];
            s.x += v.x; s.y += v.y; s.z += v.z; s.w += v.w;
        }
        *(float4*)&kvb[i] = s;
    }
    if (tid < 64) {
        float s = 0.f;
#pragma unroll
        for (int p = 0; p < KV_SPLIT; p++) s += g_ksump[(p * 96 + bh) * 64 + tid];
        g_ksum[bh * 64 + tid] = s;
    }
    __syncthreads();

    // B-frag layout: [part(2)][kc(4)][nt(8)][lane(32)] uint2
    char* dst = (char*)g_kvfrag + (size_t)bh * 16384;
#pragma unroll
    for (int pos = tid; pos < 1024; pos += 256) {
        const int kc = pos >> 8, nt = (pos >> 5) & 7, ln = pos & 31;
        const int e0 = kc * 16 + 2 * (ln & 3);
        const int n  = nt * 8 + (ln >> 2);
        float v0 = kvb[e0 * 64 + n],       v1 = kvb[(e0 + 1) * 64 + n];
        float v2 = kvb[(e0 + 8) * 64 + n], v3 = kvb[(e0 + 9) * 64 + n];
        uint32_t l0, l1;
        uint32_t h0 = split2h(make_float2(v0, v1), l0);
        uint32_t h1 = split2h(make_float2(v2, v3), l1);
        *(uint2*)(dst + pos * 8)        = make_uint2(h0, h1);
        *(uint2*)(dst + 8192 + pos * 8) = make_uint2(l0, l1);
    }
}

// ---------------------------------------------------------------------------
// vo_gemm: per (bh, 64-token tile): out = (q @ kv) * z, z = 1/(q.ksum+eps),
// written directly as fp16 hi fragments into g_a2s.
// ---------------------------------------------------------------------------
__global__ __launch_bounds__(128) void vo_gemm()
{
    const int bh   = blockIdx.x;
    const int tile = blockIdx.y;      // 0..48
    const int b = bh / 12, h = bh % 12;

    __shared__ char bfr[16384];
    __shared__ float ks[64];

    const int tid = threadIdx.x, lane = tid & 31, warp = tid >> 5;
    const uint32_t sb = smem_u32(bfr);

    const char* src = (const char*)g_kvfrag + (size_t)bh * 16384;
#pragma unroll
    for (int i = 0; i < 8; i++) {
        const int c = tid + i * 128;
        asm volatile("cp.async.cg.shared.global [%0], [%1], 16;"
                     :: "r"(sb + c * 16), "l"(src + c * 16));
    }
    asm volatile("cp.async.commit_group;");
    if (tid < 64) ks[tid] = g_ksum[bh * 64 + tid];
    asm volatile("cp.async.wait_group 0;" ::: "memory");
    __syncthreads();

    const int r  = lane >> 2;
    const int c2 = 2 * (lane & 3);
    const size_t tok0 = (size_t)b * 3136 + tile * 64 + warp * 16;
    const __half* qbase = g_qkv + tok0 * 2304 + h * 64;

    uint32_t a[4][4];
    float dr = 0.f, dr8 = 0.f;
#pragma unroll
    for (int kc = 0; kc < 4; kc++) {
        const int e0 = kc * 16 + c2;
        a[kc][0] = *(const uint32_t*)(qbase + (size_t)r * 2304 + e0);
        a[kc][1] = *(const uint32_t*)(qbase + (size_t)(r + 8) * 2304 + e0);
        a[kc][2] = *(const uint32_t*)(qbase + (size_t)r * 2304 + e0 + 8);
        a[kc][3] = *(const uint32_t*)(qbase + (size_t)(r + 8) * 2304 + e0 + 8);
        float2 f0 = __half22float2(*(__half2*)&a[kc][0]);
        float2 f1 = __half22float2(*(__half2*)&a[kc][1]);
        float2 f2 = __half22float2(*(__half2*)&a[kc][2]);
        float2 f3 = __half22float2(*(__half2*)&a[kc][3]);
        dr  += f0.x * ks[e0] + f0.y * ks[e0 + 1] + f2.x * ks[e0 + 8] + f2.y * ks[e0 + 9];
        dr8 += f1.x * ks[e0] + f1.y * ks[e0 + 1] + f3.x * ks[e0 + 8] + f3.y * ks[e0 + 9];
    }
    dr  += __shfl_xor_sync(FULL_MASK, dr, 1);  dr  += __shfl_xor_sync(FULL_MASK, dr, 2);
    dr8 += __shfl_xor_sync(FULL_MASK, dr8, 1); dr8 += __shfl_xor_sync(FULL_MASK, dr8, 2);
    const float zr  = 1.0f / (dr + 1e-4f);
    const float zr8 = 1.0f / (dr8 + 1e-4f);

    float4 acc[8];
#pragma unroll
    for (int nt = 0; nt < 8; nt++) acc[nt] = make_float4(0.f, 0.f, 0.f, 0.f);

#pragma unroll
    for (int part = 0; part < 2; part++) {
#pragma unroll
        for (int kc = 0; kc < 4; kc++) {
            const char* pb = bfr + part * 8192 + kc * 2048;
            uint4 av = make_uint4(a[kc][0], a[kc][1], a[kc][2], a[kc][3]);
#pragma unroll
            for (int nt = 0; nt < 8; nt++) {
                uint2 bb = *(const uint2*)(pb + nt * 256 + lane * 8);
                mma16(acc[nt], av, bb);
            }
        }
    }

    // epilogue: hi-only fragment store into g_a2s
    const int mb = (int)(tok0 >> 7);
    const int mt = ((int)tok0 >> 4) & 7;
    char* abase = (char*)g_a2s;
#pragma unroll
    for (int nt = 0; nt < 8; nt++) {
        const int kt = h * 4 + (nt >> 1);
        char* p = abase + (((size_t)(mb * 48 + kt)) << 12) + mt * 512 + lane * 16 + (nt & 1) * 8;
        *(uint32_t*)p = cvt2h(make_float2(acc[nt].x * zr, acc[nt].y * zr));
        *(uint32_t*)(p + 4) = cvt2h(make_float2(acc[nt].z * zr8, acc[nt].w * zr8));
    }
}

// ---------------------------------------------------------------------------
extern "C" void kernel_launch(void* const* d_in, const int* in_sizes, int n_in,
                              void* d_out, int out_size)
{
    const float* x     = (const float*)d_in[0];
    const float* Wqkv  = (const float*)d_in[1];
    const float* Wproj = (const float*)d_in[2];
    const float* bproj = (const float*)d_in[3];
    float* out = (float*)d_out;

    __half* qkv_p;
    uint4 *a1s, *a2s, *b1s, *b2s;
    cudaGetSymbolAddress((void**)&qkv_p, g_qkv);
    cudaGetSymbolAddress((void**)&a1s, g_a1s);
    cudaGetSymbolAddress((void**)&a2s, g_a2s);
    cudaGetSymbolAddress((void**)&b1s, g_b1s);
    cudaGetSymbolAddress((void**)&b2s, g_b2s);

    // 0) pre-split weights + input into fp16 fragment tiles
    split_b<<<2304 / 8, 256>>>(Wqkv,  b1s, 768);
    split_b<<<768 / 8, 256>>>(Wproj, b2s, 768);
    split_a<<<M_TOK / 16, 256>>>(x, a1s, 768);

    // 1) qkv = x @ Wqkv^T -> fp16 (fused ReLU on q,k cols < 1536)
    gemm_f16<<<dim3(2304 / 128, M_TOK / 128), 256>>>(
        a1s, b1s, nullptr, qkv_p, M_TOK, 2304, 768, nullptr, 1536);

    // 2) kv and k_sum per (b,h): HMMA S-split partials + reduce (+ frag emit)
    kv_part<<<dim3(96, KV_SPLIT), 256>>>();
    kv_reduce<<<96, 256>>>();

    // 3) out = (q @ kv) * z as tensor-core GEMM -> fp16 hi fragments
    vo_gemm<<<dim3(96, 49), 128>>>();

    // 4) out = attn @ Wproj^T + bproj (fp32 out)
    gemm_f16<<<dim3(768 / 128, M_TOK / 128), 256>>>(
        a2s, b2s, out, nullptr, M_TOK, 768, 768, bproj, 0);
}